// round 10
// baseline (speedup 1.0000x reference)
#include <cuda_runtime.h>
#include <cstdint>

// ---------------- problem constants ----------------
#define DDIM    64
#define MTOT    1024
#define NTRAIN  4096
#define TM      128
#define TN      128
#define NSPLIT  (NTRAIN / TN)      // 32
#define MT      (MTOT / TM)        // 8
#define CC      901.6844f          // log2(e)/var, var = 0.0016
#define HS      450.8422f          // 0.5*CC
#define INVCC   (1.0f / 901.6844f)

__device__ float g_scratch[MTOT * NSPLIT];   // [m][split]
__device__ int   g_cnt[MT];

__device__ __forceinline__ uint32_t smem_u32(const void* p) {
    return (uint32_t)__cvta_generic_to_shared(p);
}
__device__ __forceinline__ uint32_t bf16x2_pack(float lo, float hi) {
    uint32_t r;
    asm("cvt.rn.bf16x2.f32 %0, %1, %2;" : "=r"(r) : "f"(hi), "f"(lo));
    return r;
}
__device__ __forceinline__ float ex2f(float x) {
    float y; asm("ex2.approx.f32 %0, %1;" : "=f"(y) : "f"(x)); return y;
}
__device__ __forceinline__ uint32_t sw128(uint32_t o) {
    return o ^ ((o >> 3) & 0x70);
}
__device__ __forceinline__ void ldsm4(uint32_t r[4], uint32_t addr) {
    asm volatile("ldmatrix.sync.aligned.m8n8.x4.shared.b16 {%0,%1,%2,%3}, [%4];"
                 : "=r"(r[0]), "=r"(r[1]), "=r"(r[2]), "=r"(r[3]) : "r"(addr));
}
__device__ __forceinline__ void mma16816(float d[4], const uint32_t a[4],
                                         uint32_t b0, uint32_t b1) {
    asm volatile("mma.sync.aligned.m16n8k16.row.col.f32.bf16.bf16.f32 "
                 "{%0,%1,%2,%3}, {%4,%5,%6,%7}, {%8,%9}, {%0,%1,%2,%3};"
                 : "+f"(d[0]), "+f"(d[1]), "+f"(d[2]), "+f"(d[3])
                 : "r"(a[0]), "r"(a[1]), "r"(a[2]), "r"(a[3]),
                   "r"(b0), "r"(b1));
}
// release-publish counter arrive; acq_rel so the winner also acquires
__device__ __forceinline__ int atom_arrive(int* p) {
    int old;
    asm volatile("atom.add.acq_rel.gpu.s32 %0, [%1], 1;"
                 : "=r"(old) : "l"(p) : "memory");
    return old;
}

__global__ __launch_bounds__(256, 2)
void kde_mma(const float* __restrict__ test_x,
             const float* __restrict__ train_x,
             float* __restrict__ out)
{
    __shared__ __align__(1024) unsigned char Asm[TM * 128];
    __shared__ __align__(1024) unsigned char Bsm[TN * 128];
    __shared__ float hsa[TM];
    __shared__ float hsb[TN];

    const int tid = threadIdx.x;
    const int wid = tid >> 5;       // 8 warps: one m16 strip each
    const int lid = tid & 31;
    const int m0  = blockIdx.x * TM;
    const int n0  = blockIdx.y * TN;

    // ---- Convert phase: 8 threads/row, 2xLDG.128 + 3-shfl norm + STS.128 ----
    {
        const float4* ta = (const float4*)(test_x + (size_t)m0 * DDIM);
        #pragma unroll
        for (int i = 0; i < 4; i++) {             // A: 1024 chunks
            int idx = i * 256 + tid;
            int r = idx >> 3, j = idx & 7;
            float4 v0 = ta[idx * 2], v1 = ta[idx * 2 + 1];
            float s = v0.x*v0.x + v0.y*v0.y + v0.z*v0.z + v0.w*v0.w
                    + v1.x*v1.x + v1.y*v1.y + v1.z*v1.z + v1.w*v1.w;
            s += __shfl_xor_sync(~0u, s, 1);
            s += __shfl_xor_sync(~0u, s, 2);
            s += __shfl_xor_sync(~0u, s, 4);
            if (j == 0) hsa[r] = HS * s;
            uint4 pk = make_uint4(bf16x2_pack(v0.x, v0.y), bf16x2_pack(v0.z, v0.w),
                                  bf16x2_pack(v1.x, v1.y), bf16x2_pack(v1.z, v1.w));
            *(uint4*)(Asm + sw128((uint32_t)(r * 128 + j * 16))) = pk;
        }
        const float4* tb = (const float4*)(train_x + (size_t)n0 * DDIM);
        #pragma unroll
        for (int i = 0; i < 4; i++) {             // B: 1024 chunks
            int idx = i * 256 + tid;
            int r = idx >> 3, j = idx & 7;
            float4 v0 = tb[idx * 2], v1 = tb[idx * 2 + 1];
            float s = v0.x*v0.x + v0.y*v0.y + v0.z*v0.z + v0.w*v0.w
                    + v1.x*v1.x + v1.y*v1.y + v1.z*v1.z + v1.w*v1.w;
            s += __shfl_xor_sync(~0u, s, 1);
            s += __shfl_xor_sync(~0u, s, 2);
            s += __shfl_xor_sync(~0u, s, 4);
            if (j == 0) hsb[r] = HS * s;
            uint4 pk = make_uint4(bf16x2_pack(v0.x, v0.y), bf16x2_pack(v0.z, v0.w),
                                  bf16x2_pack(v1.x, v1.y), bf16x2_pack(v1.z, v1.w));
            *(uint4*)(Bsm + sw128((uint32_t)(r * 128 + j * 16))) = pk;
        }
    }
    __syncthreads();

    const int g  = lid >> 2;
    const int tk = lid & 3;
    const uint32_t baseA = smem_u32(Asm);
    const uint32_t baseB = smem_u32(Bsm);

    // per-warp conservative flush threshold (exact: exp2(x)=0 in fp32, x<=-150)
    float thr;
    {
        float va = hsa[wid * 16 + (lid & 15)];
        float vb = fminf(fminf(hsb[lid], hsb[lid + 32]),
                         fminf(hsb[lid + 64], hsb[lid + 96]));
        #pragma unroll
        for (int s = 8; s; s >>= 1) va = fminf(va, __shfl_xor_sync(~0u, va, s));
        #pragma unroll
        for (int s = 16; s; s >>= 1) vb = fminf(vb, __shfl_xor_sync(~0u, vb, s));
        thr = (va + vb - 151.0f) * INVCC;
    }

    // A fragments for this warp's m16 strip (resident all loop)
    uint32_t aF[4][4];
    {
        int arow = wid * 16 + (lid & 7) + ((lid >> 3) & 1) * 8;
        int acol = (lid >> 4) * 16;
        #pragma unroll
        for (int ks = 0; ks < 4; ks++)
            ldsm4(aF[ks], baseA + sw128((uint32_t)(arow * 128 + ks * 32 + acol)));
    }
    uint32_t bAddr4[4];
    {
        int rowb = ((lid >> 4) & 1) * 8 + (lid & 7);
        int colb = ((lid >> 3) & 1) * 16;
        #pragma unroll
        for (int ks = 0; ks < 4; ks++)
            bAddr4[ks] = baseB + sw128((uint32_t)(rowb * 128 + ks * 32 + colb));
    }

    const float hra0 = hsa[wid * 16 + g];
    const float hra1 = hsa[wid * 16 + g + 8];
    float acc0 = 0.f, acc1 = 0.f;    // complete row sums for rows g, g+8

    #pragma unroll
    for (int p = 0; p < 8; p++) {                 // 8 pairs of 8-col chunks
        const uint32_t boff = (uint32_t)p * 2048; // +16 rows; swizzle-invariant
        uint32_t bF[4][4];
        #pragma unroll
        for (int ks = 0; ks < 4; ks++)
            ldsm4(bF[ks], bAddr4[ks] + boff);

        float d[2][4] = {{0.f,0.f,0.f,0.f},{0.f,0.f,0.f,0.f}};
        #pragma unroll
        for (int ks = 0; ks < 4; ks++) {
            mma16816(d[0], aF[ks], bF[ks][0], bF[ks][1]);
            mma16816(d[1], aF[ks], bF[ks][2], bF[ks][3]);
        }

        float m0x = fmaxf(fmaxf(d[0][0], d[0][1]), fmaxf(d[0][2], d[0][3]));
        float m1x = fmaxf(fmaxf(d[1][0], d[1][1]), fmaxf(d[1][2], d[1][3]));
        float mx  = fmaxf(m0x, m1x);

        if (mx > thr) {   // rare exact path
            float2 hb0 = *(const float2*)&hsb[p * 16 + tk * 2];
            float2 hb1 = *(const float2*)&hsb[p * 16 + 8 + tk * 2];
            #pragma unroll
            for (int c = 0; c < 2; c++) {
                float hbx = c ? hb1.x : hb0.x;
                float hby = c ? hb1.y : hb0.y;
                acc0 += ex2f(fmaf(d[c][0], CC, -(hra0 + hbx)))
                      + ex2f(fmaf(d[c][1], CC, -(hra0 + hby)));
                acc1 += ex2f(fmaf(d[c][2], CC, -(hra1 + hbx)))
                      + ex2f(fmaf(d[c][3], CC, -(hra1 + hby)));
            }
        }
    }

    // ---- lane-reduce over tk; lane tk==0 writes complete row partials ----
    acc0 += __shfl_xor_sync(~0u, acc0, 1);
    acc0 += __shfl_xor_sync(~0u, acc0, 2);
    acc1 += __shfl_xor_sync(~0u, acc1, 1);
    acc1 += __shfl_xor_sync(~0u, acc1, 2);
    if (tk == 0) {
        g_scratch[(size_t)(m0 + wid * 16 + g) * NSPLIT + blockIdx.y]     = acc0;
        g_scratch[(size_t)(m0 + wid * 16 + g + 8) * NSPLIT + blockIdx.y] = acc1;
    }
    __syncthreads();   // all scratch STGs ordered before the release-arrive

    // ---- counter + winner tail, entirely in warp 0 (no smem, no barrier) ----
    if (wid == 0) {
        int old = 0;
        if (lid == 0) old = atom_arrive(&g_cnt[blockIdx.x]);
        old = __shfl_sync(~0u, old, 0);
        if (old == NSPLIT - 1) {                 // last CTA of this m-row
            if (lid == 0) g_cnt[blockIdx.x] = 0; // reset for graph replay
            #pragma unroll
            for (int rr = 0; rr < 4; rr++) {     // 4 rows per lane
                int m = m0 + lid * 4 + rr;
                const float4* pr = (const float4*)&g_scratch[(size_t)m * NSPLIT];
                float s = 0.f;
                #pragma unroll
                for (int j = 0; j < NSPLIT / 4; j++) {
                    float4 v = pr[j];
                    s += (v.x + v.y) + (v.z + v.w);
                }
                out[m] = s * (9.973557010f / 4096.0f);  // rsqrt(2*pi*var)/N
            }
        }
    }
}

extern "C" void kernel_launch(void* const* d_in, const int* in_sizes, int n_in,
                              void* d_out, int out_size)
{
    const float* test_x  = (const float*)d_in[0];   // [1024,64]
    const float* train_x = (const float*)d_in[1];   // [4096,64]
    float* out = (float*)d_out;                     // [1024]

    dim3 grid(MT, NSPLIT);   // (8,32) = 256 CTAs, one wave @ occ 2
    kde_mma<<<grid, 256>>>(test_x, train_x, out);
}

// round 11
// speedup vs baseline: 1.0408x; 1.0408x over previous
#include <cuda_runtime.h>
#include <cstdint>

// ---------------- problem constants ----------------
#define DDIM    64
#define MTOT    1024
#define NTRAIN  4096
#define TM      128
#define TN      128
#define NSPLIT  (NTRAIN / TN)      // 32
#define MT      (MTOT / TM)        // 8
#define CC      901.6844f          // log2(e)/var, var = 0.0016
#define HS      450.8422f          // 0.5*CC
#define INVCC   (1.0f / 901.6844f)

// ---------------- device-global staging ----------------
// Fragments in exact mma.m16n8k16 register layout:
// A: [rb(64)][ks(4)][lane(32)] uint4 = (a0,a1,a2,a3)
// B: [nbp(256)][ks(4)][lane(32)] uint4 = (b0,b1 even 8-col block, b0,b1 odd)
__device__ uint4 g_afrag[64 * 4 * 32];
__device__ uint4 g_bfrag[256 * 4 * 32];
__device__ float g_hsa[MTOT];         // HS * ||a||^2 (exact fp32)
__device__ float g_hsb[NTRAIN];
__device__ float g_scratch[MTOT * NSPLIT];   // [m][split]
__device__ int   g_cnt[MT];

__device__ __forceinline__ uint32_t bf16x2_pack(float lo, float hi) {
    uint32_t r;
    asm("cvt.rn.bf16x2.f32 %0, %1, %2;" : "=r"(r) : "f"(hi), "f"(lo));
    return r;
}
__device__ __forceinline__ float ex2f(float x) {
    float y; asm("ex2.approx.f32 %0, %1;" : "=f"(y) : "f"(x)); return y;
}
__device__ __forceinline__ void mma16816(float d[4], const uint32_t a[4],
                                         uint32_t b0, uint32_t b1) {
    asm volatile("mma.sync.aligned.m16n8k16.row.col.f32.bf16.bf16.f32 "
                 "{%0,%1,%2,%3}, {%4,%5,%6,%7}, {%8,%9}, {%0,%1,%2,%3};"
                 : "+f"(d[0]), "+f"(d[1]), "+f"(d[2]), "+f"(d[3])
                 : "r"(a[0]), "r"(a[1]), "r"(a[2]), "r"(a[3]),
                   "r"(b0), "r"(b1));
}

// ---- Kernel 1: one-shot fragment conversion + norms (8 threads/row) ----
__global__ __launch_bounds__(256)
void kde_prep(const float* __restrict__ test_x,
              const float* __restrict__ train_x)
{
    const int gid = blockIdx.x * 256 + threadIdx.x;   // 0..40959
    const int row = gid >> 3;
    const int j   = gid & 7;
    const bool isA = (row < MTOT);
    const int  r   = isA ? row : row - MTOT;
    const float4* src =
        (const float4*)((isA ? test_x : train_x) + (size_t)r * DDIM) + j * 2;

    float4 v0 = src[0], v1 = src[1];
    float s = v0.x*v0.x + v0.y*v0.y + v0.z*v0.z + v0.w*v0.w
            + v1.x*v1.x + v1.y*v1.y + v1.z*v1.z + v1.w*v1.w;
    s += __shfl_xor_sync(~0u, s, 1);
    s += __shfl_xor_sync(~0u, s, 2);
    s += __shfl_xor_sync(~0u, s, 4);
    if (j == 0) (isA ? g_hsa : g_hsb)[r] = HS * s;

    uint32_t p[4] = { bf16x2_pack(v0.x, v0.y), bf16x2_pack(v0.z, v0.w),
                      bf16x2_pack(v1.x, v1.y), bf16x2_pack(v1.z, v1.w) };
    int ks = j >> 1, jh = j & 1;
    int laneb = (r & 7) * 4;
    if (isA) {
        int aidx = jh * 2 + ((r >> 3) & 1);
        char* dst = (char*)g_afrag +
            ((((r >> 4) * 4 + ks) * 32 + laneb) * 16 + aidx * 4);
        #pragma unroll
        for (int t = 0; t < 4; t++) *(uint32_t*)(dst + t * 16) = p[t];
    } else {
        int comp = ((r >> 3) & 1) * 2 + jh;
        char* dst = (char*)g_bfrag +
            ((((r >> 4) * 4 + ks) * 32 + laneb) * 16 + comp * 4);
        #pragma unroll
        for (int t = 0; t < 4; t++) *(uint32_t*)(dst + t * 16) = p[t];
    }
}

// ---- Kernel 2: fragment-direct GEMM + fused deterministic reduction ----
__global__ __launch_bounds__(256, 3)
void kde_mma(float* __restrict__ out)
{
    __shared__ float red[2][TM];
    __shared__ int is_last;

    const int tid = threadIdx.x;
    const int wid = tid >> 5;
    const int lid = tid & 31;
    const int m0  = blockIdx.x * TM;
    const int n0  = blockIdx.y * TN;

    const int mw = wid & 3;        // warp rows: m0+mw*32 .. +31
    const int nw = wid >> 2;       // warp cols: n0+nw*64 .. +63
    const int g  = lid >> 2;
    const int tk = lid & 3;

    // per-warp conservative flush threshold (exact: exp2(x)=0 in fp32, x<=-150)
    float thr;
    {
        float va = g_hsa[m0 + mw * 32 + lid];
        float vb = fminf(g_hsb[n0 + nw * 64 + lid],
                         g_hsb[n0 + nw * 64 + 32 + lid]);
        #pragma unroll
        for (int s = 16; s; s >>= 1) {
            va = fminf(va, __shfl_xor_sync(~0u, va, s));
            vb = fminf(vb, __shfl_xor_sync(~0u, vb, s));
        }
        thr = (va + vb - 151.0f) * INVCC;
    }

    // A fragments: 8 coalesced LDG.128, resident all loop
    uint4 aF[2][4];
    {
        const int rbb = (m0 >> 4) + mw * 2;
        #pragma unroll
        for (int mt = 0; mt < 2; mt++)
            #pragma unroll
            for (int ks = 0; ks < 4; ks++)
                aF[mt][ks] = g_afrag[(((rbb + mt) * 4 + ks) << 5) + lid];
    }

    float acc[2][2] = {{0.f, 0.f}, {0.f, 0.f}};
    const int nbpb = (n0 >> 4) + nw * 4;

    #pragma unroll
    for (int p = 0; p < 4; p++) {
        uint4 bF[4];
        #pragma unroll
        for (int ks = 0; ks < 4; ks++)
            bF[ks] = g_bfrag[(((nbpb + p) * 4 + ks) << 5) + lid];

        float d[2][2][4];
        #pragma unroll
        for (int mt = 0; mt < 2; mt++)
            #pragma unroll
            for (int c = 0; c < 2; c++)
                #pragma unroll
                for (int q = 0; q < 4; q++) d[mt][c][q] = 0.f;

        #pragma unroll
        for (int ks = 0; ks < 4; ks++)
            #pragma unroll
            for (int mt = 0; mt < 2; mt++) {
                mma16816(d[mt][0], (const uint32_t*)&aF[mt][ks], bF[ks].x, bF[ks].y);
                mma16816(d[mt][1], (const uint32_t*)&aF[mt][ks], bF[ks].z, bF[ks].w);
            }

        float m01 = fmaxf(fmaxf(d[0][0][0], d[0][0][1]), fmaxf(d[0][0][2], d[0][0][3]));
        float m23 = fmaxf(fmaxf(d[0][1][0], d[0][1][1]), fmaxf(d[0][1][2], d[0][1][3]));
        float m45 = fmaxf(fmaxf(d[1][0][0], d[1][0][1]), fmaxf(d[1][0][2], d[1][0][3]));
        float m67 = fmaxf(fmaxf(d[1][1][0], d[1][1][1]), fmaxf(d[1][1][2], d[1][1][3]));
        float mx  = fmaxf(fmaxf(m01, m23), fmaxf(m45, m67));

        if (mx > thr) {   // rare exact path
            const int cb = n0 + nw * 64 + p * 16;
            float2 hb0 = *(const float2*)&g_hsb[cb + tk * 2];
            float2 hb1 = *(const float2*)&g_hsb[cb + 8 + tk * 2];
            #pragma unroll
            for (int mt = 0; mt < 2; mt++) {
                float hra0 = g_hsa[m0 + mw * 32 + mt * 16 + g];
                float hra1 = g_hsa[m0 + mw * 32 + mt * 16 + g + 8];
                #pragma unroll
                for (int c = 0; c < 2; c++) {
                    float hbx = c ? hb1.x : hb0.x;
                    float hby = c ? hb1.y : hb0.y;
                    acc[mt][0] += ex2f(fmaf(d[mt][c][0], CC, -(hra0 + hbx)))
                                + ex2f(fmaf(d[mt][c][1], CC, -(hra0 + hby)));
                    acc[mt][1] += ex2f(fmaf(d[mt][c][2], CC, -(hra1 + hbx)))
                                + ex2f(fmaf(d[mt][c][3], CC, -(hra1 + hby)));
                }
            }
        }
    }

    // ---- reduce across the 4 col-pair lanes; per-(nw) row sums ----
    #pragma unroll
    for (int mt = 0; mt < 2; mt++)
        #pragma unroll
        for (int rr = 0; rr < 2; rr++) {
            float v = acc[mt][rr];
            v += __shfl_xor_sync(~0u, v, 1);
            v += __shfl_xor_sync(~0u, v, 2);
            acc[mt][rr] = v;
        }
    if (tk == 0) {
        #pragma unroll
        for (int mt = 0; mt < 2; mt++) {
            red[nw][mw * 32 + mt * 16 + g]     = acc[mt][0];
            red[nw][mw * 32 + mt * 16 + g + 8] = acc[mt][1];
        }
    }
    __syncthreads();

    if (tid < TM)
        g_scratch[(size_t)(m0 + tid) * NSPLIT + blockIdx.y] =
            red[0][tid] + red[1][tid];

    // ---- last block per m-tile: deterministic final reduction ----
    if (tid == 0) {
        __threadfence();
        int old = atomicAdd(&g_cnt[blockIdx.x], 1);
        is_last = (old == NSPLIT - 1);
        if (is_last) g_cnt[blockIdx.x] = 0;   // reset for graph replay
    }
    __syncthreads();
    if (is_last) {
        __threadfence();
        if (tid < TM) {
            const float4* pr = (const float4*)&g_scratch[(size_t)(m0 + tid) * NSPLIT];
            float s = 0.f;
            #pragma unroll
            for (int j = 0; j < NSPLIT / 4; j++) {
                float4 v = pr[j];
                s += (v.x + v.y) + (v.z + v.w);
            }
            out[m0 + tid] = s * (9.973557010f / 4096.0f);  // rsqrt(2*pi*var)/N
        }
    }
}

extern "C" void kernel_launch(void* const* d_in, const int* in_sizes, int n_in,
                              void* d_out, int out_size)
{
    const float* test_x  = (const float*)d_in[0];   // [1024,64]
    const float* train_x = (const float*)d_in[1];   // [4096,64]
    float* out = (float*)d_out;                     // [1024]

    kde_prep<<<(MTOT + NTRAIN) * 8 / 256, 256>>>(test_x, train_x);
    dim3 grid(MT, NSPLIT);   // (8,32) = 256 CTAs, ~one wave @ occ 3
    kde_mma<<<grid, 256>>>(out);
}

// round 12
// speedup vs baseline: 1.2107x; 1.1632x over previous
#include <cuda_runtime.h>
#include <cstdint>

// ---------------- problem constants ----------------
#define DDIM    64
#define MTOT    1024
#define NTRAIN  4096
#define TM      128
#define TN      256
#define NSPLIT  (NTRAIN / TN)      // 16
#define MT      (MTOT / TM)        // 8
#define CC      901.6844f          // log2(e)/var, var = 0.0016
#define HS      450.8422f          // 0.5*CC
#define INVCC   (1.0f / 901.6844f)
#define NTHR    512
#define SCW     64                 // scratch width: 16 splits * 4 n-warps

__device__ float g_scratch[MTOT * SCW];   // [m][split*4 + nw]
__device__ int   g_cnt[MT];

// dynamic smem layout (bytes)
#define OFF_A    0                     // 128 rows * 128B, SW128
#define OFF_B    16384                 // 256 rows * 128B, SW128
#define OFF_HSA  49152                 // 128 f32
#define OFF_HSB  49664                 // 256 f32
#define SMEM_BYTES 50688

__device__ __forceinline__ uint32_t smem_u32(const void* p) {
    return (uint32_t)__cvta_generic_to_shared(p);
}
__device__ __forceinline__ uint32_t bf16x2_pack(float lo, float hi) {
    uint32_t r;
    asm("cvt.rn.bf16x2.f32 %0, %1, %2;" : "=r"(r) : "f"(hi), "f"(lo));
    return r;
}
__device__ __forceinline__ float ex2f(float x) {
    float y; asm("ex2.approx.f32 %0, %1;" : "=f"(y) : "f"(x)); return y;
}
__device__ __forceinline__ uint32_t sw128(uint32_t o) {
    return o ^ ((o >> 3) & 0x70);
}
__device__ __forceinline__ void ldsm4(uint32_t r[4], uint32_t addr) {
    asm volatile("ldmatrix.sync.aligned.m8n8.x4.shared.b16 {%0,%1,%2,%3}, [%4];"
                 : "=r"(r[0]), "=r"(r[1]), "=r"(r[2]), "=r"(r[3]) : "r"(addr));
}
__device__ __forceinline__ void mma16816(float d[4], const uint32_t a[4],
                                         uint32_t b0, uint32_t b1) {
    asm volatile("mma.sync.aligned.m16n8k16.row.col.f32.bf16.bf16.f32 "
                 "{%0,%1,%2,%3}, {%4,%5,%6,%7}, {%8,%9}, {%0,%1,%2,%3};"
                 : "+f"(d[0]), "+f"(d[1]), "+f"(d[2]), "+f"(d[3])
                 : "r"(a[0]), "r"(a[1]), "r"(a[2]), "r"(a[3]),
                   "r"(b0), "r"(b1));
}

__global__ __launch_bounds__(NTHR, 1)
void kde_mma(const float* __restrict__ test_x,
             const float* __restrict__ train_x,
             float* __restrict__ out)
{
    extern __shared__ char sm[];
    float* hsa = (float*)(sm + OFF_HSA);
    float* hsb = (float*)(sm + OFF_HSB);
    __shared__ int is_last;

    const int tid = threadIdx.x;
    const int wid = tid >> 5;
    const int lid = tid & 31;
    const int m0  = blockIdx.x * TM;
    const int n0  = blockIdx.y * TN;

    // ---- Convert phase: 8 threads/row, 2xLDG.128 + 3-shfl norm + STS.128 ----
    {
        const float4* ta = (const float4*)(test_x + (size_t)m0 * DDIM);
        #pragma unroll
        for (int i = 0; i < 2; i++) {             // A: 1024 chunks
            int idx = i * NTHR + tid;
            int r = idx >> 3, j = idx & 7;
            float4 v0 = ta[idx * 2], v1 = ta[idx * 2 + 1];
            float s = v0.x*v0.x + v0.y*v0.y + v0.z*v0.z + v0.w*v0.w
                    + v1.x*v1.x + v1.y*v1.y + v1.z*v1.z + v1.w*v1.w;
            s += __shfl_xor_sync(~0u, s, 1);
            s += __shfl_xor_sync(~0u, s, 2);
            s += __shfl_xor_sync(~0u, s, 4);
            if (j == 0) hsa[r] = HS * s;
            uint4 pk = make_uint4(bf16x2_pack(v0.x, v0.y), bf16x2_pack(v0.z, v0.w),
                                  bf16x2_pack(v1.x, v1.y), bf16x2_pack(v1.z, v1.w));
            *(uint4*)(sm + OFF_A + sw128((uint32_t)(r * 128 + j * 16))) = pk;
        }
        const float4* tb = (const float4*)(train_x + (size_t)n0 * DDIM);
        #pragma unroll
        for (int i = 0; i < 4; i++) {             // B: 2048 chunks
            int idx = i * NTHR + tid;
            int r = idx >> 3, j = idx & 7;
            float4 v0 = tb[idx * 2], v1 = tb[idx * 2 + 1];
            float s = v0.x*v0.x + v0.y*v0.y + v0.z*v0.z + v0.w*v0.w
                    + v1.x*v1.x + v1.y*v1.y + v1.z*v1.z + v1.w*v1.w;
            s += __shfl_xor_sync(~0u, s, 1);
            s += __shfl_xor_sync(~0u, s, 2);
            s += __shfl_xor_sync(~0u, s, 4);
            if (j == 0) hsb[r] = HS * s;
            uint4 pk = make_uint4(bf16x2_pack(v0.x, v0.y), bf16x2_pack(v0.z, v0.w),
                                  bf16x2_pack(v1.x, v1.y), bf16x2_pack(v1.z, v1.w));
            *(uint4*)(sm + OFF_B + sw128((uint32_t)(r * 128 + j * 16))) = pk;
        }
    }
    __syncthreads();

    // ---- Warp tiling: 4 m-warps x 4 n-warps; warp tile 32 x 64 ----
    const int mw = wid & 3;
    const int nw = wid >> 2;
    const int g  = lid >> 2;
    const int tk = lid & 3;
    const uint32_t baseA = smem_u32(sm + OFF_A);
    const uint32_t baseB = smem_u32(sm + OFF_B);

    // per-warp conservative flush threshold (exact: exp2(x)=0 in fp32, x<=-150)
    float thr;
    {
        float va = hsa[mw * 32 + lid];
        float vb = fminf(hsb[nw * 64 + lid], hsb[nw * 64 + 32 + lid]);
        #pragma unroll
        for (int s = 16; s; s >>= 1) {
            va = fminf(va, __shfl_xor_sync(~0u, va, s));
            vb = fminf(vb, __shfl_xor_sync(~0u, vb, s));
        }
        thr = (va + vb - 151.0f) * INVCC;
    }

    uint32_t aF[2][4][4];
    {
        int arow = mw * 32 + (lid & 7) + ((lid >> 3) & 1) * 8;
        int acol = (lid >> 4) * 16;
        #pragma unroll
        for (int mt = 0; mt < 2; mt++)
            #pragma unroll
            for (int ks = 0; ks < 4; ks++)
                ldsm4(aF[mt][ks],
                      baseA + sw128((uint32_t)((arow + mt * 16) * 128 + ks * 32 + acol)));
    }
    uint32_t bAddr4[4];
    {
        int rowb = nw * 64 + ((lid >> 4) & 1) * 8 + (lid & 7);
        int colb = ((lid >> 3) & 1) * 16;
        #pragma unroll
        for (int ks = 0; ks < 4; ks++)
            bAddr4[ks] = baseB + sw128((uint32_t)(rowb * 128 + ks * 32 + colb));
    }

    float hra[2][2];
    #pragma unroll
    for (int mt = 0; mt < 2; mt++) {
        hra[mt][0] = hsa[mw * 32 + mt * 16 + g];
        hra[mt][1] = hsa[mw * 32 + mt * 16 + g + 8];
    }

    float acc[2][2] = {{0.f, 0.f}, {0.f, 0.f}};

    #pragma unroll
    for (int p = 0; p < 4; p++) {                 // 4 pairs of 8-col chunks
        const uint32_t boff = (uint32_t)p * 2048; // +16 rows; swizzle-invariant
        uint32_t bF[4][4];
        #pragma unroll
        for (int ks = 0; ks < 4; ks++)
            ldsm4(bF[ks], bAddr4[ks] + boff);

        float d[2][2][4];
        #pragma unroll
        for (int mt = 0; mt < 2; mt++)
            #pragma unroll
            for (int c = 0; c < 2; c++)
                #pragma unroll
                for (int q = 0; q < 4; q++) d[mt][c][q] = 0.f;

        #pragma unroll
        for (int ks = 0; ks < 4; ks++)
            #pragma unroll
            for (int mt = 0; mt < 2; mt++) {
                mma16816(d[mt][0], aF[mt][ks], bF[ks][0], bF[ks][1]);
                mma16816(d[mt][1], aF[mt][ks], bF[ks][2], bF[ks][3]);
            }

        float m01 = fmaxf(fmaxf(d[0][0][0], d[0][0][1]), fmaxf(d[0][0][2], d[0][0][3]));
        float m23 = fmaxf(fmaxf(d[0][1][0], d[0][1][1]), fmaxf(d[0][1][2], d[0][1][3]));
        float m45 = fmaxf(fmaxf(d[1][0][0], d[1][0][1]), fmaxf(d[1][0][2], d[1][0][3]));
        float m67 = fmaxf(fmaxf(d[1][1][0], d[1][1][1]), fmaxf(d[1][1][2], d[1][1][3]));
        float mx  = fmaxf(fmaxf(m01, m23), fmaxf(m45, m67));

        if (mx > thr) {   // rare exact path
            float2 hb0 = *(const float2*)&hsb[nw * 64 + p * 16 + tk * 2];
            float2 hb1 = *(const float2*)&hsb[nw * 64 + p * 16 + 8 + tk * 2];
            #pragma unroll
            for (int mt = 0; mt < 2; mt++)
                #pragma unroll
                for (int c = 0; c < 2; c++) {
                    float hbx = c ? hb1.x : hb0.x;
                    float hby = c ? hb1.y : hb0.y;
                    acc[mt][0] += ex2f(fmaf(d[mt][c][0], CC, -(hra[mt][0] + hbx)))
                                + ex2f(fmaf(d[mt][c][1], CC, -(hra[mt][0] + hby)));
                    acc[mt][1] += ex2f(fmaf(d[mt][c][2], CC, -(hra[mt][1] + hbx)))
                                + ex2f(fmaf(d[mt][c][3], CC, -(hra[mt][1] + hby)));
                }
        }
    }

    // ---- lane-reduce over tk; tk==0 lanes write strip sums STRAIGHT to scratch ----
    #pragma unroll
    for (int mt = 0; mt < 2; mt++)
        #pragma unroll
        for (int rr = 0; rr < 2; rr++) {
            float v = acc[mt][rr];
            v += __shfl_xor_sync(~0u, v, 1);
            v += __shfl_xor_sync(~0u, v, 2);
            acc[mt][rr] = v;
        }
    if (tk == 0) {
        const int col = blockIdx.y * 4 + nw;
        #pragma unroll
        for (int mt = 0; mt < 2; mt++) {
            int r0 = m0 + mw * 32 + mt * 16 + g;
            g_scratch[(size_t)r0 * SCW + col]       = acc[mt][0];
            g_scratch[(size_t)(r0 + 8) * SCW + col] = acc[mt][1];
        }
    }
    __syncthreads();   // order all STGs before the (cumulative) release below

    // ---- last block per m-tile: deterministic final reduction ----
    if (tid == 0) {
        __threadfence();                          // cumulative release
        int old = atomicAdd(&g_cnt[blockIdx.x], 1);
        is_last = (old == NSPLIT - 1);
        if (is_last) g_cnt[blockIdx.x] = 0;       // reset for graph replay
    }
    __syncthreads();
    if (is_last) {
        __threadfence();                          // acquire
        if (tid < TM) {
            const float4* pr = (const float4*)&g_scratch[(size_t)(m0 + tid) * SCW];
            float s = 0.f;
            #pragma unroll
            for (int j = 0; j < SCW / 4; j++) {   // 16 LDG.128, MLP 16
                float4 v = pr[j];
                s += (v.x + v.y) + (v.z + v.w);
            }
            out[m0 + tid] = s * (9.973557010f / 4096.0f);  // rsqrt(2*pi*var)/N
        }
    }
}

extern "C" void kernel_launch(void* const* d_in, const int* in_sizes, int n_in,
                              void* d_out, int out_size)
{
    const float* test_x  = (const float*)d_in[0];   // [1024,64]
    const float* train_x = (const float*)d_in[1];   // [4096,64]
    float* out = (float*)d_out;                     // [1024]

    static int inited = 0;
    if (!inited) {
        cudaFuncSetAttribute(kde_mma,
                             cudaFuncAttributeMaxDynamicSharedMemorySize,
                             SMEM_BYTES);
        inited = 1;
    }
    dim3 grid(MT, NSPLIT);   // (8,16) = 128 CTAs, one per SM, single wave
    kde_mma<<<grid, NTHR, SMEM_BYTES>>>(test_x, train_x, out);
}